// round 7
// baseline (speedup 1.0000x reference)
#include <cuda_runtime.h>
#include <cuda_fp16.h>
#include <cuda_bf16.h>
#include <cstdint>

#define EMBED   1024
#define HEADS   16
#define HD      64
#define BATCH   8
#define SEQ     1024
#define ROWS    8192
#define QKV_N   3072
#define KDIM    1024
#define LOG2E   1.4426950408889634f
#define QSCALE  (0.125f * LOG2E)
#define INV2048 4.8828125e-4f

// ---------------- scratch ----------------
// GEMM A/B operands: fp16 hi (row stride 1024) + fp8 [row][kblk64][hi 64B | lo 64B] (row stride 2048 B)
__device__ __align__(1024) __half   g_xh16[ROWS * EMBED];
__device__ __align__(1024) uint8_t  g_x8[ROWS * EMBED * 2];
__device__ __align__(1024) __half   g_wqh16[QKV_N * EMBED];
__device__ __align__(1024) uint8_t  g_wq8[QKV_N * EMBED * 2];
__device__ __align__(1024) __half   g_wph16[EMBED * EMBED];
__device__ __align__(1024) uint8_t  g_wp8[EMBED * EMBED * 2];
__device__ __align__(1024) __half   g_ah16[ROWS * EMBED];
__device__ __align__(1024) uint8_t  g_a8[ROWS * EMBED * 2];
// attention operands (bf16 hi/lo, validated path)
__device__ __align__(1024) __nv_bfloat16 g_qh[BATCH * HEADS * SEQ * HD];
__device__ __align__(1024) __nv_bfloat16 g_ql[BATCH * HEADS * SEQ * HD];
__device__ __align__(1024) __nv_bfloat16 g_kh[BATCH * HEADS * SEQ * HD];
__device__ __align__(1024) __nv_bfloat16 g_kl[BATCH * HEADS * SEQ * HD];
__device__ __align__(1024) __nv_bfloat16 g_vh[BATCH * HEADS * SEQ * HD];
__device__ __align__(1024) __nv_bfloat16 g_vl[BATCH * HEADS * SEQ * HD];

// ---------------- helpers ----------------
__device__ __forceinline__ uint32_t smem_u32(const void* p) {
    uint32_t a;
    asm("{ .reg .u64 t; cvta.to.shared.u64 t, %1; cvt.u32.u64 %0, t; }" : "=r"(a) : "l"(p));
    return a;
}
__device__ __forceinline__ float ex2f(float x) {
    float y; asm("ex2.approx.ftz.f32 %0, %1;" : "=f"(y) : "f"(x)); return y;
}
__device__ __forceinline__ uint32_t sw128(uint32_t o) { return o ^ ((o >> 3) & 0x70); }

#define CP_ASYNC(dst, src) \
    asm volatile("cp.async.cg.shared.global [%0], [%1], 16;" :: "r"(dst), "l"(src) : "memory")
#define CP_COMMIT() asm volatile("cp.async.commit_group;" ::: "memory")
#define CP_WAIT1()  asm volatile("cp.async.wait_group 1;" ::: "memory")
#define CP_WAIT0()  asm volatile("cp.async.wait_group 0;" ::: "memory")

__device__ __forceinline__ void ldsm4(uint32_t r[4], uint32_t addr) {
    asm volatile("ldmatrix.sync.aligned.m8n8.x4.shared.b16 {%0,%1,%2,%3}, [%4];"
                 : "=r"(r[0]), "=r"(r[1]), "=r"(r[2]), "=r"(r[3]) : "r"(addr));
}
__device__ __forceinline__ void ldsm4t(uint32_t r[4], uint32_t addr) {
    asm volatile("ldmatrix.sync.aligned.m8n8.x4.trans.shared.b16 {%0,%1,%2,%3}, [%4];"
                 : "=r"(r[0]), "=r"(r[1]), "=r"(r[2]), "=r"(r[3]) : "r"(addr));
}
__device__ __forceinline__ void mma_bf16(float c[4], const uint32_t a[4],
                                         uint32_t b0, uint32_t b1) {
    asm volatile(
        "mma.sync.aligned.m16n8k16.row.col.f32.bf16.bf16.f32 "
        "{%0,%1,%2,%3}, {%4,%5,%6,%7}, {%8,%9}, {%0,%1,%2,%3};"
        : "+f"(c[0]), "+f"(c[1]), "+f"(c[2]), "+f"(c[3])
        : "r"(a[0]), "r"(a[1]), "r"(a[2]), "r"(a[3]), "r"(b0), "r"(b1));
}
__device__ __forceinline__ void mma_f16(float c[4], const uint32_t a[4],
                                        uint32_t b0, uint32_t b1) {
    asm volatile(
        "mma.sync.aligned.m16n8k16.row.col.f32.f16.f16.f32 "
        "{%0,%1,%2,%3}, {%4,%5,%6,%7}, {%8,%9}, {%0,%1,%2,%3};"
        : "+f"(c[0]), "+f"(c[1]), "+f"(c[2]), "+f"(c[3])
        : "r"(a[0]), "r"(a[1]), "r"(a[2]), "r"(a[3]), "r"(b0), "r"(b1));
}
__device__ __forceinline__ void mma_e4m3(float c[4], const uint32_t a[4],
                                         uint32_t b0, uint32_t b1) {
    asm volatile(
        "mma.sync.aligned.m16n8k32.row.col.f32.e4m3.e4m3.f32 "
        "{%0,%1,%2,%3}, {%4,%5,%6,%7}, {%8,%9}, {%0,%1,%2,%3};"
        : "+f"(c[0]), "+f"(c[1]), "+f"(c[2]), "+f"(c[3])
        : "r"(a[0]), "r"(a[1]), "r"(a[2]), "r"(a[3]), "r"(b0), "r"(b1));
}

// (v0,v1) -> fp16x2 (v0 low half), e4m3x2 of values (v0 low byte), e4m3x2 of residual*2048
__device__ __forceinline__ void cvt_pair(float v0, float v1, uint32_t& h16,
                                         uint16_t& h8, uint16_t& l8) {
    asm("cvt.rn.f16x2.f32 %0, %1, %2;" : "=r"(h16) : "f"(v1), "f"(v0));
    half2 hh = *reinterpret_cast<half2*>(&h16);
    float2 hf = __half22float2(hh);
    asm("cvt.rn.satfinite.e4m3x2.f32 %0, %1, %2;" : "=h"(h8) : "f"(v1), "f"(v0));
    asm("cvt.rn.satfinite.e4m3x2.f32 %0, %1, %2;"
        : "=h"(l8) : "f"((v1 - hf.y) * 2048.f), "f"((v0 - hf.x) * 2048.f));
}
// bf16 hi/lo split (attention operands)
__device__ __forceinline__ void split2(float v0, float v1, uint32_t& hi, uint32_t& lo) {
    __nv_bfloat162 h2 = __floats2bfloat162_rn(v0, v1);
    float2 hf = __bfloat1622float2(h2);
    __nv_bfloat162 l2 = __floats2bfloat162_rn(v0 - hf.x, v1 - hf.y);
    hi = *reinterpret_cast<uint32_t*>(&h2);
    lo = *reinterpret_cast<uint32_t*>(&l2);
}

// ---------------- fused input conversion ----------------
#define XU  (ROWS * EMBED / 8)
#define WQU (QKV_N * EMBED / 8)
#define WPU (EMBED * EMBED / 8)
#define TOTU (XU + WQU + WPU)

__global__ __launch_bounds__(256)
void split_all(const float* __restrict__ x, const float* __restrict__ wq,
               const float* __restrict__ wp)
{
    const int u = blockIdx.x * 256 + threadIdx.x;
    if (u >= TOTU) return;
    const float* src; __half* hdst; uint8_t* pdst; int local;
    if (u < XU)            { src = x;  hdst = g_xh16;  pdst = g_x8;  local = u; }
    else if (u < XU + WQU) { src = wq; hdst = g_wqh16; pdst = g_wq8; local = u - XU; }
    else                   { src = wp; hdst = g_wph16; pdst = g_wp8; local = u - XU - WQU; }

    float4 a = ((const float4*)src)[local * 2];
    float4 b = ((const float4*)src)[local * 2 + 1];
    float v[8] = {a.x, a.y, a.z, a.w, b.x, b.y, b.z, b.w};
    uint32_t H16[4];
    uint16_t H8[4], L8[4];
#pragma unroll
    for (int j = 0; j < 4; j++) cvt_pair(v[2*j], v[2*j+1], H16[j], H8[j], L8[j]);

    ((uint4*)hdst)[local] = make_uint4(H16[0], H16[1], H16[2], H16[3]);
    const int e0 = local * 8;
    const int base = (e0 >> 10) * 2048 + ((e0 & 1023) >> 6) * 128 + (e0 & 63);
    *(uint2*)(pdst + base) = make_uint2(
        (uint32_t)H8[0] | ((uint32_t)H8[1] << 16),
        (uint32_t)H8[2] | ((uint32_t)H8[3] << 16));
    *(uint2*)(pdst + base + 64) = make_uint2(
        (uint32_t)L8[0] | ((uint32_t)L8[1] << 16),
        (uint32_t)L8[2] | ((uint32_t)L8[3] << 16));
}

// ---------------- GEMM: C = A @ B^T + bias (fp16 hi + fp8 correction) ----------------
// 128x128 tile, K-tile 64, 256 thr / 8 warps (4m x 2n), cp.async double-buffered.
// Stage: AH16 16K | A8 16K | BH16 16K | B8 16K
#define STG_BYTES 65536
#define SMEM_BYTES (2 * STG_BYTES)

template <int MODE>
__global__ __launch_bounds__(256, 1)
void gemm_mma(const float* __restrict__ bias, float* __restrict__ Cout)
{
    extern __shared__ char smem[];
    const uint32_t sb = smem_u32(smem);
    const int tid = threadIdx.x;
    const int lane = tid & 31;
    const int wid  = tid >> 5;
    const int warp_m = wid & 3;
    const int warp_n = wid >> 2;
    const int m0 = blockIdx.y * 128;
    const int n0 = blockIdx.x * 128;

    const __half*  Ah = (MODE == 0) ? g_xh16  : g_ah16;
    const uint8_t* A8 = (MODE == 0) ? g_x8    : g_a8;
    const __half*  Bh = (MODE == 0) ? g_wqh16 : g_wph16;
    const uint8_t* B8 = (MODE == 0) ? g_wq8   : g_wp8;

    const int r0  = tid >> 3;
    const int seg = tid & 7;

    auto issue = [&](int stage, int kt) {
        const uint32_t s0 = sb + stage * STG_BYTES;
        const int kb = (kt >> 6) * 128;
#pragma unroll
        for (int u = 0; u < 4; u++) {
            const int row = r0 + u * 32;
            const uint32_t so = sw128((uint32_t)(row * 128 + seg * 16));
            CP_ASYNC(s0 +         so, (const char*)(Ah + (m0 + row) * KDIM + kt + seg * 8));
            CP_ASYNC(s0 + 16384 + so, (const char*)(A8 + (m0 + row) * 2048 + kb + seg * 16));
            CP_ASYNC(s0 + 32768 + so, (const char*)(Bh + (n0 + row) * KDIM + kt + seg * 8));
            CP_ASYNC(s0 + 49152 + so, (const char*)(B8 + (n0 + row) * 2048 + kb + seg * 16));
        }
    };

    float c[2][8][4], cc[2][8][4];
#pragma unroll
    for (int mt = 0; mt < 2; mt++)
#pragma unroll
        for (int nt = 0; nt < 8; nt++)
#pragma unroll
            for (int j = 0; j < 4; j++) { c[mt][nt][j] = 0.f; cc[mt][nt][j] = 0.f; }

    issue(0, 0);
    CP_COMMIT();

    const int NIT = KDIM / 64;
    for (int it = 0; it < NIT; it++) {
        const int s = it & 1;
        if (it + 1 < NIT) { issue(s ^ 1, (it + 1) * 64); CP_COMMIT(); CP_WAIT1(); }
        else              { CP_WAIT0(); }
        __syncthreads();

        const uint32_t sAH = sb + s * STG_BYTES;
        const uint32_t sA8 = sAH + 16384;
        const uint32_t sBH = sAH + 32768;
        const uint32_t sB8 = sAH + 49152;

        // ---- fp16 hi pass: 4 k16-steps ----
#pragma unroll
        for (int ks = 0; ks < 4; ks++) {
            uint32_t ah[2][4];
#pragma unroll
            for (int mt = 0; mt < 2; mt++) {
                const int arow = warp_m * 32 + mt * 16 + (lane & 7) + ((lane >> 3) & 1) * 8;
                const uint32_t off =
                    sw128((uint32_t)(arow * 128 + (ks * 2 + (lane >> 4)) * 16));
                ldsm4(ah[mt], sAH + off);
            }
            uint32_t bh[8][2];
#pragma unroll
            for (int p = 0; p < 4; p++) {
                const int brow = warp_n * 64 + p * 16 + (lane >> 4) * 8 + (lane & 7);
                const uint32_t off =
                    sw128((uint32_t)(brow * 128 + (ks * 2 + ((lane >> 3) & 1)) * 16));
                uint32_t r[4];
                ldsm4(r, sBH + off);
                bh[2*p][0] = r[0]; bh[2*p][1] = r[1];
                bh[2*p+1][0] = r[2]; bh[2*p+1][1] = r[3];
            }
#pragma unroll
            for (int mt = 0; mt < 2; mt++)
#pragma unroll
                for (int nt = 0; nt < 8; nt++)
                    mma_f16(c[mt][nt], ah[mt], bh[nt][0], bh[nt][1]);
        }

        // ---- fp8 correction: 2 k32-steps, passes Ahi*Blo + Alo*Bhi ----
#pragma unroll
        for (int s8 = 0; s8 < 2; s8++) {
            uint32_t a8h[2][4], a8l[2][4];
#pragma unroll
            for (int mt = 0; mt < 2; mt++) {
                const int arow = warp_m * 32 + mt * 16 + (lane & 7) + ((lane >> 3) & 1) * 8;
                const uint32_t oh =
                    sw128((uint32_t)(arow * 128 + (s8 * 2 + (lane >> 4)) * 16));
                const uint32_t ol =
                    sw128((uint32_t)(arow * 128 + 64 + (s8 * 2 + (lane >> 4)) * 16));
                ldsm4(a8h[mt], sA8 + oh);
                ldsm4(a8l[mt], sA8 + ol);
            }
            uint32_t b8h[8][2], b8l[8][2];
#pragma unroll
            for (int p = 0; p < 4; p++) {
                const int brow = warp_n * 64 + p * 16 + (lane >> 4) * 8 + (lane & 7);
                const uint32_t oh =
                    sw128((uint32_t)(brow * 128 + (s8 * 2 + ((lane >> 3) & 1)) * 16));
                const uint32_t ol =
                    sw128((uint32_t)(brow * 128 + 64 + (s8 * 2 + ((lane >> 3) & 1)) * 16));
                uint32_t rh[4], rl[4];
                ldsm4(rh, sB8 + oh);
                ldsm4(rl, sB8 + ol);
                b8h[2*p][0] = rh[0]; b8h[2*p][1] = rh[1];
                b8h[2*p+1][0] = rh[2]; b8h[2*p+1][1] = rh[3];
                b8l[2*p][0] = rl[0]; b8l[2*p][1] = rl[1];
                b8l[2*p+1][0] = rl[2]; b8l[2*p+1][1] = rl[3];
            }
#pragma unroll
            for (int mt = 0; mt < 2; mt++)
#pragma unroll
                for (int nt = 0; nt < 8; nt++) {
                    mma_e4m3(cc[mt][nt], a8h[mt], b8l[nt][0], b8l[nt][1]);
                    mma_e4m3(cc[mt][nt], a8l[mt], b8h[nt][0], b8h[nt][1]);
                }
        }
        __syncthreads();
    }

    const int g = lane >> 2, t = lane & 3;
#pragma unroll
    for (int mt = 0; mt < 2; mt++) {
#pragma unroll
        for (int nt = 0; nt < 8; nt++) {
            const int col = n0 + warp_n * 64 + nt * 8 + t * 2;
            const float b0 = __ldg(&bias[col]), b1 = __ldg(&bias[col + 1]);
#pragma unroll
            for (int half_ = 0; half_ < 2; half_++) {
                const int row = m0 + warp_m * 32 + mt * 16 + g + half_ * 8;
                float v0 = c[mt][nt][half_ * 2 + 0] + cc[mt][nt][half_ * 2 + 0] * INV2048 + b0;
                float v1 = c[mt][nt][half_ * 2 + 1] + cc[mt][nt][half_ * 2 + 1] * INV2048 + b1;
                if (MODE == 0) {
                    const int b_ = row >> 10, n = row & 1023;
                    const int ty = col >> 10, rem = col & 1023;
                    const int h  = rem >> 6, d = rem & 63;
                    if (ty == 0) { v0 *= QSCALE; v1 *= QSCALE; }
                    const int idx = (((b_ * HEADS + h) * SEQ) + n) * HD + d;
                    uint32_t hi, lo;
                    split2(v0, v1, hi, lo);
                    __nv_bfloat16* dh = (ty == 0) ? g_qh : (ty == 1) ? g_kh : g_vh;
                    __nv_bfloat16* dl = (ty == 0) ? g_ql : (ty == 1) ? g_kl : g_vl;
                    *(uint32_t*)(dh + idx) = hi;
                    *(uint32_t*)(dl + idx) = lo;
                } else {
                    *(float2*)(Cout + row * EMBED + col) = make_float2(v0, v1);
                }
            }
        }
    }
}

// ---------------- tensor-core flash attention (validated round-4 path) ----------------
#define ATTN_SMEM 98304
#define NKT (SEQ / 64)

__global__ __launch_bounds__(256, 1)
void attn_tc()
{
    extern __shared__ char smem[];
    const uint32_t sb = smem_u32(smem);
    const int tid = threadIdx.x, lane = tid & 31, w = tid >> 5;
    const int bh = blockIdx.x, qt = blockIdx.y;
    const int g = lane >> 2, t = lane & 3;

    const uint32_t SQH = sb, SQL = sb + 16384;

    auto issueQ = [&]() {
        const int row0 = tid >> 3, seg = tid & 7;
#pragma unroll
        for (int u = 0; u < 4; u++) {
            const int row = row0 + u * 32;
            const uint32_t off = sw128((uint32_t)(row * 128 + seg * 16));
            const int e = ((bh * SEQ) + qt * 128 + row) * HD + seg * 8;
            CP_ASYNC(SQH + off, (const char*)(g_qh + e));
            CP_ASYNC(SQL + off, (const char*)(g_ql + e));
        }
    };
    auto issueKV = [&](int s, int kt) {
        const uint32_t base = sb + 32768 + s * 32768;
        const int row0 = tid >> 3, seg = tid & 7;
#pragma unroll
        for (int u = 0; u < 2; u++) {
            const int row = row0 + u * 32;
            const uint32_t off = sw128((uint32_t)(row * 128 + seg * 16));
            const int e = ((bh * SEQ) + kt + row) * HD + seg * 8;
            CP_ASYNC(base +         off, (const char*)(g_kh + e));
            CP_ASYNC(base +  8192 + off, (const char*)(g_kl + e));
            CP_ASYNC(base + 16384 + off, (const char*)(g_vh + e));
            CP_ASYNC(base + 24576 + off, (const char*)(g_vl + e));
        }
    };

    issueQ(); issueKV(0, 0); CP_COMMIT();
    issueKV(1, 64); CP_COMMIT();
    CP_WAIT1(); __syncthreads();

    uint32_t qh[4][4], ql[4][4];
    {
        const int arow = w * 16 + (lane & 7) + ((lane >> 3) & 1) * 8;
#pragma unroll
        for (int ks = 0; ks < 4; ks++) {
            const uint32_t off = sw128((uint32_t)(arow * 128 + (ks * 2 + (lane >> 4)) * 16));
            ldsm4(qh[ks], SQH + off);
            ldsm4(ql[ks], SQL + off);
        }
    }

    float o[8][4];
#pragma unroll
    for (int nt = 0; nt < 8; nt++)
#pragma unroll
        for (int j = 0; j < 4; j++) o[nt][j] = 0.f;
    float m0 = -1e30f, m1 = -1e30f, l0 = 0.f, l1 = 0.f;

    for (int it = 0; it < NKT; it++) {
        if (it > 0) {
            if (it + 1 < NKT) CP_WAIT1(); else CP_WAIT0();
            __syncthreads();
        }
        const uint32_t KH = sb + 32768 + (it & 1) * 32768;
        const uint32_t KL = KH + 8192, VH = KH + 16384, VL = KH + 24576;

        float c[8][4];
#pragma unroll
        for (int nt = 0; nt < 8; nt++)
#pragma unroll
            for (int j = 0; j < 4; j++) c[nt][j] = 0.f;

#pragma unroll
        for (int ks = 0; ks < 4; ks++) {
            uint32_t kh[4][4], kl[4][4];
#pragma unroll
            for (int p = 0; p < 4; p++) {
                const int brow = p * 16 + (lane >> 4) * 8 + (lane & 7);
                const uint32_t off =
                    sw128((uint32_t)(brow * 128 + (ks * 2 + ((lane >> 3) & 1)) * 16));
                ldsm4(kh[p], KH + off);
                ldsm4(kl[p], KL + off);
            }
#pragma unroll
            for (int p = 0; p < 4; p++) {
                mma_bf16(c[2*p],   qh[ks], kh[p][0], kh[p][1]);
                mma_bf16(c[2*p],   qh[ks], kl[p][0], kl[p][1]);
                mma_bf16(c[2*p],   ql[ks], kh[p][0], kh[p][1]);
                mma_bf16(c[2*p+1], qh[ks], kh[p][2], kh[p][3]);
                mma_bf16(c[2*p+1], qh[ks], kl[p][2], kl[p][3]);
                mma_bf16(c[2*p+1], ql[ks], kh[p][2], kh[p][3]);
            }
        }

        float mx0 = -1e30f, mx1 = -1e30f;
#pragma unroll
        for (int nt = 0; nt < 8; nt++) {
            mx0 = fmaxf(mx0, fmaxf(c[nt][0], c[nt][1]));
            mx1 = fmaxf(mx1, fmaxf(c[nt][2], c[nt][3]));
        }
        mx0 = fmaxf(mx0, __shfl_xor_sync(0xffffffffu, mx0, 1));
        mx0 = fmaxf(mx0, __shfl_xor_sync(0xffffffffu, mx0, 2));
        mx1 = fmaxf(mx1, __shfl_xor_sync(0xffffffffu, mx1, 1));
        mx1 = fmaxf(mx1, __shfl_xor_sync(0xffffffffu, mx1, 2));
        const float mn0 = fmaxf(m0, mx0), mn1 = fmaxf(m1, mx1);
        const float cor0 = ex2f(m0 - mn0), cor1 = ex2f(m1 - mn1);
        m0 = mn0; m1 = mn1;
        float s0 = 0.f, s1 = 0.f;
#pragma unroll
        for (int nt = 0; nt < 8; nt++) {
            c[nt][0] = ex2f(c[nt][0] - m0);
            c[nt][1] = ex2f(c[nt][1] - m0);
            c[nt][2] = ex2f(c[nt][2] - m1);
            c[nt][3] = ex2f(c[nt][3] - m1);
            s0 += c[nt][0] + c[nt][1];
            s1 += c[nt][2] + c[nt][3];
            o[nt][0] *= cor0; o[nt][1] *= cor0;
            o[nt][2] *= cor1; o[nt][3] *= cor1;
        }
        s0 += __shfl_xor_sync(0xffffffffu, s0, 1);
        s0 += __shfl_xor_sync(0xffffffffu, s0, 2);
        s1 += __shfl_xor_sync(0xffffffffu, s1, 1);
        s1 += __shfl_xor_sync(0xffffffffu, s1, 2);
        l0 = l0 * cor0 + s0;
        l1 = l1 * cor1 + s1;

#pragma unroll
        for (int ks = 0; ks < 4; ks++) {
            uint32_t ph[4], pl[4];
            split2(c[2*ks][0],   c[2*ks][1],   ph[0], pl[0]);
            split2(c[2*ks][2],   c[2*ks][3],   ph[1], pl[1]);
            split2(c[2*ks+1][0], c[2*ks+1][1], ph[2], pl[2]);
            split2(c[2*ks+1][2], c[2*ks+1][3], ph[3], pl[3]);

            uint32_t vh[4][4], vl[4][4];
#pragma unroll
            for (int p = 0; p < 4; p++) {
                const int krow = ks * 16 + (lane & 15);
                const int ncol = p * 16 + (lane >> 4) * 8;
                const uint32_t off = sw128((uint32_t)(krow * 128 + ncol * 2));
                ldsm4t(vh[p], VH + off);
                ldsm4t(vl[p], VL + off);
            }
#pragma unroll
            for (int p = 0; p < 4; p++) {
                mma_bf16(o[2*p],   ph, vh[p][0], vh[p][1]);
                mma_bf16(o[2*p],   pl, vh[p][0], vh[p][1]);
                mma_bf16(o[2*p],   ph, vl[p][0], vl[p][1]);
                mma_bf16(o[2*p+1], ph, vh[p][2], vh[p][3]);
                mma_bf16(o[2*p+1], pl, vh[p][2], vh[p][3]);
                mma_bf16(o[2*p+1], ph, vl[p][2], vl[p][3]);
            }
        }
        __syncthreads();
        if (it + 2 < NKT) { issueKV(it & 1, (it + 2) * 64); CP_COMMIT(); }
    }

    // epilogue: write fp16-hi + fp8 hi/lo for the proj GEMM
    const float i0 = 1.f / l0, i1 = 1.f / l1;
    const int b_ = bh >> 4, h = bh & 15;
    const int r0 = b_ * SEQ + qt * 128 + w * 16 + g;
#pragma unroll
    for (int nt = 0; nt < 8; nt++) {
        const int col = h * HD + nt * 8 + t * 2;
        const int kb = col >> 6, off = col & 63;
#pragma unroll
        for (int half_ = 0; half_ < 2; half_++) {
            const int row = r0 + half_ * 8;
            const float v0 = o[nt][half_ * 2 + 0] * ((half_ == 0) ? i0 : i1);
            const float v1 = o[nt][half_ * 2 + 1] * ((half_ == 0) ? i0 : i1);
            uint32_t h16; uint16_t h8, l8;
            cvt_pair(v0, v1, h16, h8, l8);
            *(uint32_t*)(g_ah16 + row * EMBED + col) = h16;
            const int base = row * 2048 + kb * 128 + off;
            *(uint16_t*)(g_a8 + base)      = h8;
            *(uint16_t*)(g_a8 + base + 64) = l8;
        }
    }
}

// ---------------------------------------------------------------------------
extern "C" void kernel_launch(void* const* d_in, const int* in_sizes, int n_in,
                              void* d_out, int out_size)
{
    (void)in_sizes; (void)n_in; (void)out_size;
    const float* x      = (const float*)d_in[0];
    const float* w_qkv  = (const float*)d_in[1];
    const float* b_qkv  = (const float*)d_in[2];
    const float* w_proj = (const float*)d_in[3];
    const float* b_proj = (const float*)d_in[4];
    float* out = (float*)d_out;

    cudaFuncSetAttribute(gemm_mma<0>, cudaFuncAttributeMaxDynamicSharedMemorySize, SMEM_BYTES);
    cudaFuncSetAttribute(gemm_mma<1>, cudaFuncAttributeMaxDynamicSharedMemorySize, SMEM_BYTES);
    cudaFuncSetAttribute(attn_tc, cudaFuncAttributeMaxDynamicSharedMemorySize, ATTN_SMEM);

    split_all<<<(TOTU + 255) / 256, 256>>>(x, w_qkv, w_proj);
    gemm_mma<0><<<dim3(QKV_N / 128, ROWS / 128), 256, SMEM_BYTES>>>(b_qkv, nullptr);
    attn_tc<<<dim3(BATCH * HEADS, SEQ / 128), 256, ATTN_SMEM>>>();
    gemm_mma<1><<<dim3(EMBED / 128, ROWS / 128), 256, SMEM_BYTES>>>(b_proj, out);
}

// round 8
// speedup vs baseline: 1.1248x; 1.1248x over previous
#include <cuda_runtime.h>
#include <cuda_bf16.h>
#include <cstdint>

#define EMBED   1024
#define HEADS   16
#define HD      64
#define BATCH   8
#define SEQ     1024
#define ROWS    8192
#define QKV_N   3072
#define KDIM    1024
#define LOG2E   1.4426950408889634f
#define QSCALE  (0.125f * LOG2E)          // fold 1/sqrt(64) and log2(e) into Q

// ---------------- scratch (device globals; allocation-free) ----------------
__device__ __align__(1024) __nv_bfloat16 g_xh[ROWS * EMBED];
__device__ __align__(1024) __nv_bfloat16 g_xl[ROWS * EMBED];
__device__ __align__(1024) __nv_bfloat16 g_wqh[QKV_N * EMBED];
__device__ __align__(1024) __nv_bfloat16 g_wql[QKV_N * EMBED];
__device__ __align__(1024) __nv_bfloat16 g_wph[EMBED * EMBED];
__device__ __align__(1024) __nv_bfloat16 g_wpl[EMBED * EMBED];
// Q/K/V as bf16 hi/lo, layout [B,H,N,D]; Q pre-scaled by QSCALE
__device__ __align__(1024) __nv_bfloat16 g_qh[BATCH * HEADS * SEQ * HD];
__device__ __align__(1024) __nv_bfloat16 g_ql[BATCH * HEADS * SEQ * HD];
__device__ __align__(1024) __nv_bfloat16 g_kh[BATCH * HEADS * SEQ * HD];
__device__ __align__(1024) __nv_bfloat16 g_kl[BATCH * HEADS * SEQ * HD];
__device__ __align__(1024) __nv_bfloat16 g_vh[BATCH * HEADS * SEQ * HD];
__device__ __align__(1024) __nv_bfloat16 g_vl[BATCH * HEADS * SEQ * HD];
__device__ __align__(1024) __nv_bfloat16 g_ah[ROWS * EMBED];      // attention out hi
__device__ __align__(1024) __nv_bfloat16 g_al[ROWS * EMBED];      // attention out lo

// ---------------- helpers ----------------
__device__ __forceinline__ uint32_t smem_u32(const void* p) {
    uint32_t a;
    asm("{ .reg .u64 t; cvta.to.shared.u64 t, %1; cvt.u32.u64 %0, t; }" : "=r"(a) : "l"(p));
    return a;
}
__device__ __forceinline__ float ex2f(float x) {
    float y; asm("ex2.approx.ftz.f32 %0, %1;" : "=f"(y) : "f"(x)); return y;
}
__device__ __forceinline__ uint32_t sw128(uint32_t o) { return o ^ ((o >> 3) & 0x70); }

#define CP_ASYNC(dst, src) \
    asm volatile("cp.async.cg.shared.global [%0], [%1], 16;" :: "r"(dst), "l"(src) : "memory")
#define CP_COMMIT() asm volatile("cp.async.commit_group;" ::: "memory")
#define CP_WAIT1()  asm volatile("cp.async.wait_group 1;" ::: "memory")
#define CP_WAIT0()  asm volatile("cp.async.wait_group 0;" ::: "memory")

__device__ __forceinline__ void ldsm4(uint32_t r[4], uint32_t addr) {
    asm volatile("ldmatrix.sync.aligned.m8n8.x4.shared.b16 {%0,%1,%2,%3}, [%4];"
                 : "=r"(r[0]), "=r"(r[1]), "=r"(r[2]), "=r"(r[3]) : "r"(addr));
}
__device__ __forceinline__ void ldsm4t(uint32_t r[4], uint32_t addr) {
    asm volatile("ldmatrix.sync.aligned.m8n8.x4.trans.shared.b16 {%0,%1,%2,%3}, [%4];"
                 : "=r"(r[0]), "=r"(r[1]), "=r"(r[2]), "=r"(r[3]) : "r"(addr));
}
__device__ __forceinline__ void mma_bf16(float c[4], const uint32_t a[4],
                                         uint32_t b0, uint32_t b1) {
    asm volatile(
        "mma.sync.aligned.m16n8k16.row.col.f32.bf16.bf16.f32 "
        "{%0,%1,%2,%3}, {%4,%5,%6,%7}, {%8,%9}, {%0,%1,%2,%3};"
        : "+f"(c[0]), "+f"(c[1]), "+f"(c[2]), "+f"(c[3])
        : "r"(a[0]), "r"(a[1]), "r"(a[2]), "r"(a[3]), "r"(b0), "r"(b1));
}

// split (v0,v1) -> packed bf16x2 hi + residual lo (v0 in low half)
__device__ __forceinline__ void split2(float v0, float v1, uint32_t& hi, uint32_t& lo) {
    __nv_bfloat162 h2 = __floats2bfloat162_rn(v0, v1);
    float2 hf = __bfloat1622float2(h2);
    __nv_bfloat162 l2 = __floats2bfloat162_rn(v0 - hf.x, v1 - hf.y);
    hi = *reinterpret_cast<uint32_t*>(&h2);
    lo = *reinterpret_cast<uint32_t*>(&l2);
}

// ---------------- fused input split: x, w_qkv, w_proj -> bf16 hi/lo ----------------
#define XU  (ROWS * EMBED / 8)
#define WQU (QKV_N * EMBED / 8)
#define WPU (EMBED * EMBED / 8)
#define TOTU (XU + WQU + WPU)

__global__ __launch_bounds__(256)
void split_all(const float* __restrict__ x, const float* __restrict__ wq,
               const float* __restrict__ wp)
{
    const int u = blockIdx.x * 256 + threadIdx.x;
    if (u >= TOTU) return;
    const float* src; __nv_bfloat16* h; __nv_bfloat16* l; int local;
    if (u < XU)            { src = x;  h = g_xh;  l = g_xl;  local = u; }
    else if (u < XU + WQU) { src = wq; h = g_wqh; l = g_wql; local = u - XU; }
    else                   { src = wp; h = g_wph; l = g_wpl; local = u - XU - WQU; }

    float4 a = ((const float4*)src)[local * 2];
    float4 b = ((const float4*)src)[local * 2 + 1];
    float v[8] = {a.x, a.y, a.z, a.w, b.x, b.y, b.z, b.w};
    __nv_bfloat16 hb[8], lb[8];
#pragma unroll
    for (int j = 0; j < 8; j++) {
        hb[j] = __float2bfloat16(v[j]);
        lb[j] = __float2bfloat16(v[j] - __bfloat162float(hb[j]));
    }
    ((uint4*)h)[local] = *(uint4*)hb;
    ((uint4*)l)[local] = *(uint4*)lb;
}

// ---------------- mma.sync split-bf16 GEMM: C = A @ B^T + bias ----------------
// 128x128 tile, K-tile 64, 256 thr / 8 warps (4m x 2n), 3-stage cp.async pipeline,
// single __syncthreads per iteration.
#define STG_BYTES 65536            // Ah,Al,Bh,Bl = 4 x 16KB per stage
#define SMEM_BYTES (3 * STG_BYTES)

template <int MODE>
__global__ __launch_bounds__(256, 1)
void gemm_mma(const float* __restrict__ bias, float* __restrict__ Cout)
{
    extern __shared__ char smem[];
    const uint32_t sb = smem_u32(smem);
    const int tid = threadIdx.x;
    const int lane = tid & 31;
    const int wid  = tid >> 5;
    const int warp_m = wid & 3;
    const int warp_n = wid >> 2;
    const int m0 = blockIdx.y * 128;
    const int n0 = blockIdx.x * 128;

    const __nv_bfloat16* Ah = (MODE == 0) ? g_xh  : g_ah;
    const __nv_bfloat16* Al = (MODE == 0) ? g_xl  : g_al;
    const __nv_bfloat16* Bh = (MODE == 0) ? g_wqh : g_wph;
    const __nv_bfloat16* Bl = (MODE == 0) ? g_wql : g_wpl;

    const int r0  = tid >> 3;
    const int seg = tid & 7;

    auto issue = [&](int stage, int kt) {
        const uint32_t s0 = sb + stage * STG_BYTES;
#pragma unroll
        for (int u = 0; u < 4; u++) {
            const int row = r0 + u * 32;
            const uint32_t so = sw128((uint32_t)(row * 128 + seg * 16));
            const int ae = (m0 + row) * KDIM + kt + seg * 8;
            const int be = (n0 + row) * KDIM + kt + seg * 8;
            CP_ASYNC(s0 +         so, (const char*)(Ah + ae));
            CP_ASYNC(s0 + 16384 + so, (const char*)(Al + ae));
            CP_ASYNC(s0 + 32768 + so, (const char*)(Bh + be));
            CP_ASYNC(s0 + 49152 + so, (const char*)(Bl + be));
        }
    };

    float c[2][8][4];
#pragma unroll
    for (int mt = 0; mt < 2; mt++)
#pragma unroll
        for (int nt = 0; nt < 8; nt++)
#pragma unroll
            for (int j = 0; j < 4; j++) c[mt][nt][j] = 0.f;

    issue(0, 0);  CP_COMMIT();
    issue(1, 64); CP_COMMIT();

    const int NIT = KDIM / 64;             // 16
    for (int it = 0; it < NIT; it++) {
        if (it + 1 < NIT) CP_WAIT1(); else CP_WAIT0();
        __syncthreads();                   // single barrier per iteration
        if (it + 2 < NIT) { issue((it + 2) % 3, (it + 2) * 64); CP_COMMIT(); }

        const uint32_t sA_h = sb + (it % 3) * STG_BYTES;
        const uint32_t sA_l = sA_h + 16384;
        const uint32_t sB_h = sA_h + 32768;
        const uint32_t sB_l = sA_h + 49152;

#pragma unroll
        for (int ks = 0; ks < 4; ks++) {
            uint32_t ah[2][4], al[2][4];
#pragma unroll
            for (int mt = 0; mt < 2; mt++) {
                const int arow = warp_m * 32 + mt * 16 + (lane & 7) + ((lane >> 3) & 1) * 8;
                const int aseg = ks * 2 + (lane >> 4);
                const uint32_t off = sw128((uint32_t)(arow * 128 + aseg * 16));
                ldsm4(ah[mt], sA_h + off);
                ldsm4(al[mt], sA_l + off);
            }
            uint32_t bh[8][2], bl[8][2];
#pragma unroll
            for (int p = 0; p < 4; p++) {
                const int brow = warp_n * 64 + p * 16 + (lane >> 4) * 8 + (lane & 7);
                const int bseg = ks * 2 + ((lane >> 3) & 1);
                const uint32_t off = sw128((uint32_t)(brow * 128 + bseg * 16));
                uint32_t rh[4], rl[4];
                ldsm4(rh, sB_h + off);
                ldsm4(rl, sB_l + off);
                bh[2*p][0] = rh[0]; bh[2*p][1] = rh[1];
                bh[2*p+1][0] = rh[2]; bh[2*p+1][1] = rh[3];
                bl[2*p][0] = rl[0]; bl[2*p][1] = rl[1];
                bl[2*p+1][0] = rl[2]; bl[2*p+1][1] = rl[3];
            }
#pragma unroll
            for (int mt = 0; mt < 2; mt++)
#pragma unroll
                for (int nt = 0; nt < 8; nt++) {
                    mma_bf16(c[mt][nt], ah[mt], bh[nt][0], bh[nt][1]);
                    mma_bf16(c[mt][nt], ah[mt], bl[nt][0], bl[nt][1]);
                    mma_bf16(c[mt][nt], al[mt], bh[nt][0], bh[nt][1]);
                }
        }
    }

    const int g = lane >> 2, t = lane & 3;
#pragma unroll
    for (int mt = 0; mt < 2; mt++) {
#pragma unroll
        for (int nt = 0; nt < 8; nt++) {
            const int col = n0 + warp_n * 64 + nt * 8 + t * 2;
            const float b0 = __ldg(&bias[col]), b1 = __ldg(&bias[col + 1]);
#pragma unroll
            for (int half = 0; half < 2; half++) {
                const int row = m0 + warp_m * 32 + mt * 16 + g + half * 8;
                float v0 = c[mt][nt][half * 2 + 0] + b0;
                float v1 = c[mt][nt][half * 2 + 1] + b1;
                if (MODE == 0) {
                    const int b_ = row >> 10, n = row & 1023;
                    const int ty = col >> 10, rem = col & 1023;
                    const int h  = rem >> 6, d = rem & 63;
                    if (ty == 0) { v0 *= QSCALE; v1 *= QSCALE; }
                    const int idx = (((b_ * HEADS + h) * SEQ) + n) * HD + d;
                    uint32_t hi, lo;
                    split2(v0, v1, hi, lo);
                    __nv_bfloat16* dh = (ty == 0) ? g_qh : (ty == 1) ? g_kh : g_vh;
                    __nv_bfloat16* dl = (ty == 0) ? g_ql : (ty == 1) ? g_kl : g_vl;
                    *(uint32_t*)(dh + idx) = hi;
                    *(uint32_t*)(dl + idx) = lo;
                } else {
                    *(float2*)(Cout + row * EMBED + col) = make_float2(v0, v1);
                }
            }
        }
    }
}

// ---------------- tensor-core flash attention ----------------
// grid (B*H, SEQ/128), 256 threads / 8 warps; warp w owns q rows w*16..w*16+15.
// smem: Qh 16K | Ql 16K | 3 KV stages x (Kh 8K | Kl 8K | Vh 8K | Vl 8K)
#define KV_STG 32768
#define ATTN_SMEM (32768 + 3 * KV_STG)
#define NKT (SEQ / 64)

__global__ __launch_bounds__(256, 1)
void attn_tc()
{
    extern __shared__ char smem[];
    const uint32_t sb = smem_u32(smem);
    const int tid = threadIdx.x, lane = tid & 31, w = tid >> 5;
    const int bh = blockIdx.x, qt = blockIdx.y;
    const int g = lane >> 2, t = lane & 3;

    const uint32_t SQH = sb, SQL = sb + 16384;

    auto issueQ = [&]() {
        const int row0 = tid >> 3, seg = tid & 7;
#pragma unroll
        for (int u = 0; u < 4; u++) {
            const int row = row0 + u * 32;
            const uint32_t off = sw128((uint32_t)(row * 128 + seg * 16));
            const int e = ((bh * SEQ) + qt * 128 + row) * HD + seg * 8;
            CP_ASYNC(SQH + off, (const char*)(g_qh + e));
            CP_ASYNC(SQL + off, (const char*)(g_ql + e));
        }
    };
    auto issueKV = [&](int s, int kt) {
        const uint32_t base = sb + 32768 + s * KV_STG;
        const int row0 = tid >> 3, seg = tid & 7;
#pragma unroll
        for (int u = 0; u < 2; u++) {
            const int row = row0 + u * 32;
            const uint32_t off = sw128((uint32_t)(row * 128 + seg * 16));
            const int e = ((bh * SEQ) + kt + row) * HD + seg * 8;
            CP_ASYNC(base +         off, (const char*)(g_kh + e));
            CP_ASYNC(base +  8192 + off, (const char*)(g_kl + e));
            CP_ASYNC(base + 16384 + off, (const char*)(g_vh + e));
            CP_ASYNC(base + 24576 + off, (const char*)(g_vl + e));
        }
    };

    issueQ(); issueKV(0, 0); CP_COMMIT();
    issueKV(1, 64); CP_COMMIT();
    CP_WAIT1(); __syncthreads();

    // Q fragments, held for whole kernel
    uint32_t qh[4][4], ql[4][4];
    {
        const int arow = w * 16 + (lane & 7) + ((lane >> 3) & 1) * 8;
#pragma unroll
        for (int ks = 0; ks < 4; ks++) {
            const uint32_t off = sw128((uint32_t)(arow * 128 + (ks * 2 + (lane >> 4)) * 16));
            ldsm4(qh[ks], SQH + off);
            ldsm4(ql[ks], SQL + off);
        }
    }

    float o[8][4];
#pragma unroll
    for (int nt = 0; nt < 8; nt++)
#pragma unroll
        for (int j = 0; j < 4; j++) o[nt][j] = 0.f;
    float m0 = -1e30f, m1 = -1e30f, l0 = 0.f, l1 = 0.f;

    for (int it = 0; it < NKT; it++) {
        if (it > 0) {
            if (it + 1 < NKT) CP_WAIT1(); else CP_WAIT0();
            __syncthreads();               // single barrier per iteration
        }
        if (it + 2 < NKT) { issueKV((it + 2) % 3, (it + 2) * 64); CP_COMMIT(); }

        const uint32_t KH = sb + 32768 + (it % 3) * KV_STG;
        const uint32_t KL = KH + 8192, VH = KH + 16384, VL = KH + 24576;

        // ---- S = Q @ K^T (3-pass split) ----
        float c[8][4];
#pragma unroll
        for (int nt = 0; nt < 8; nt++)
#pragma unroll
            for (int j = 0; j < 4; j++) c[nt][j] = 0.f;

#pragma unroll
        for (int ks = 0; ks < 4; ks++) {
            uint32_t kh[4][4], kl[4][4];
#pragma unroll
            for (int p = 0; p < 4; p++) {
                const int brow = p * 16 + (lane >> 4) * 8 + (lane & 7);
                const uint32_t off =
                    sw128((uint32_t)(brow * 128 + (ks * 2 + ((lane >> 3) & 1)) * 16));
                ldsm4(kh[p], KH + off);
                ldsm4(kl[p], KL + off);
            }
#pragma unroll
            for (int p = 0; p < 4; p++) {
                mma_bf16(c[2*p],   qh[ks], kh[p][0], kh[p][1]);
                mma_bf16(c[2*p],   qh[ks], kl[p][0], kl[p][1]);
                mma_bf16(c[2*p],   ql[ks], kh[p][0], kh[p][1]);
                mma_bf16(c[2*p+1], qh[ks], kh[p][2], kh[p][3]);
                mma_bf16(c[2*p+1], qh[ks], kl[p][2], kl[p][3]);
                mma_bf16(c[2*p+1], ql[ks], kh[p][2], kh[p][3]);
            }
        }

        // ---- online softmax (rows g and g+8; S already in log2 domain) ----
        float mx0 = -1e30f, mx1 = -1e30f;
#pragma unroll
        for (int nt = 0; nt < 8; nt++) {
            mx0 = fmaxf(mx0, fmaxf(c[nt][0], c[nt][1]));
            mx1 = fmaxf(mx1, fmaxf(c[nt][2], c[nt][3]));
        }
        mx0 = fmaxf(mx0, __shfl_xor_sync(0xffffffffu, mx0, 1));
        mx0 = fmaxf(mx0, __shfl_xor_sync(0xffffffffu, mx0, 2));
        mx1 = fmaxf(mx1, __shfl_xor_sync(0xffffffffu, mx1, 1));
        mx1 = fmaxf(mx1, __shfl_xor_sync(0xffffffffu, mx1, 2));
        const float mn0 = fmaxf(m0, mx0), mn1 = fmaxf(m1, mx1);
        const float cor0 = ex2f(m0 - mn0), cor1 = ex2f(m1 - mn1);
        m0 = mn0; m1 = mn1;
        float s0 = 0.f, s1 = 0.f;
#pragma unroll
        for (int nt = 0; nt < 8; nt++) {
            c[nt][0] = ex2f(c[nt][0] - m0);
            c[nt][1] = ex2f(c[nt][1] - m0);
            c[nt][2] = ex2f(c[nt][2] - m1);
            c[nt][3] = ex2f(c[nt][3] - m1);
            s0 += c[nt][0] + c[nt][1];
            s1 += c[nt][2] + c[nt][3];
            o[nt][0] *= cor0; o[nt][1] *= cor0;
            o[nt][2] *= cor1; o[nt][3] *= cor1;
        }
        s0 += __shfl_xor_sync(0xffffffffu, s0, 1);
        s0 += __shfl_xor_sync(0xffffffffu, s0, 2);
        s1 += __shfl_xor_sync(0xffffffffu, s1, 1);
        s1 += __shfl_xor_sync(0xffffffffu, s1, 2);
        l0 = l0 * cor0 + s0;
        l1 = l1 * cor1 + s1;

        // ---- O += P @ V (3-pass split; P frags from accum regs) ----
#pragma unroll
        for (int ks = 0; ks < 4; ks++) {
            uint32_t ph[4], pl[4];
            split2(c[2*ks][0],   c[2*ks][1],   ph[0], pl[0]);
            split2(c[2*ks][2],   c[2*ks][3],   ph[1], pl[1]);
            split2(c[2*ks+1][0], c[2*ks+1][1], ph[2], pl[2]);
            split2(c[2*ks+1][2], c[2*ks+1][3], ph[3], pl[3]);

            uint32_t vh[4][4], vl[4][4];
#pragma unroll
            for (int p = 0; p < 4; p++) {
                const int krow = ks * 16 + (lane & 15);
                const int ncol = p * 16 + (lane >> 4) * 8;
                const uint32_t off = sw128((uint32_t)(krow * 128 + ncol * 2));
                ldsm4t(vh[p], VH + off);
                ldsm4t(vl[p], VL + off);
            }
#pragma unroll
            for (int p = 0; p < 4; p++) {
                mma_bf16(o[2*p],   ph, vh[p][0], vh[p][1]);
                mma_bf16(o[2*p],   pl, vh[p][0], vh[p][1]);
                mma_bf16(o[2*p],   ph, vl[p][0], vl[p][1]);
                mma_bf16(o[2*p+1], ph, vh[p][2], vh[p][3]);
                mma_bf16(o[2*p+1], pl, vh[p][2], vh[p][3]);
                mma_bf16(o[2*p+1], ph, vl[p][2], vl[p][3]);
            }
        }
    }

    // ---- epilogue: normalize, hi/lo split, write [row, E] ----
    const float i0 = 1.f / l0, i1 = 1.f / l1;
    const int b_ = bh >> 4, h = bh & 15;
    const int r0 = b_ * SEQ + qt * 128 + w * 16 + g;
#pragma unroll
    for (int nt = 0; nt < 8; nt++) {
        const int col = h * HD + nt * 8 + t * 2;
        uint32_t hi, lo;
        split2(o[nt][0] * i0, o[nt][1] * i0, hi, lo);
        *(uint32_t*)(g_ah + r0 * EMBED + col) = hi;
        *(uint32_t*)(g_al + r0 * EMBED + col) = lo;
        split2(o[nt][2] * i1, o[nt][3] * i1, hi, lo);
        *(uint32_t*)(g_ah + (r0 + 8) * EMBED + col) = hi;
        *(uint32_t*)(g_al + (r0 + 8) * EMBED + col) = lo;
    }
}

// ---------------------------------------------------------------------------
extern "C" void kernel_launch(void* const* d_in, const int* in_sizes, int n_in,
                              void* d_out, int out_size)
{
    (void)in_sizes; (void)n_in; (void)out_size;
    const float* x      = (const float*)d_in[0];
    const float* w_qkv  = (const float*)d_in[1];
    const float* b_qkv  = (const float*)d_in[2];
    const float* w_proj = (const float*)d_in[3];
    const float* b_proj = (const float*)d_in[4];
    float* out = (float*)d_out;

    cudaFuncSetAttribute(gemm_mma<0>, cudaFuncAttributeMaxDynamicSharedMemorySize, SMEM_BYTES);
    cudaFuncSetAttribute(gemm_mma<1>, cudaFuncAttributeMaxDynamicSharedMemorySize, SMEM_BYTES);
    cudaFuncSetAttribute(attn_tc, cudaFuncAttributeMaxDynamicSharedMemorySize, ATTN_SMEM);

    split_all<<<(TOTU + 255) / 256, 256>>>(x, w_qkv, w_proj);
    gemm_mma<0><<<dim3(QKV_N / 128, ROWS / 128), 256, SMEM_BYTES>>>(b_qkv, nullptr);
    attn_tc<<<dim3(BATCH * HEADS, SEQ / 128), 256, ATTN_SMEM>>>();
    gemm_mma<1><<<dim3(EMBED / 128, ROWS / 128), 256, SMEM_BYTES>>>(b_proj, out);
}